// round 1
// baseline (speedup 1.0000x reference)
#include <cuda_runtime.h>
#include <cuda_bf16.h>
#include <cstddef>

// Problem constants
#define BATCH   8
#define SEQ     2048
#define DIM     1024
#define HEADS   16
#define HDIM    64
#define TOKENS  (BATCH * SEQ)          // 16384
#define ELEMS   (TOKENS * DIM)         // 16,777,216

// Scratch (allocation-free rule: __device__ globals)
__device__ float g_Q[ELEMS];
__device__ float g_K[ELEMS];
__device__ float g_V[ELEMS];
__device__ float g_Y[ELEMS];

// ---------------------------------------------------------------------------
// GEMM-NT: C[m,n] = sum_k A[m,k] * B[n,k]  (+ bias[n])
// A: [M,K] row-major, B: [N,K] row-major (i.e. torch Linear weight [out,in])
// Tiles: 128x128x16, 256 threads, 8x8 per-thread microtile.
// All dims are multiples of tile sizes for this problem -> no bounds checks.
// ---------------------------------------------------------------------------
#define BM 128
#define BN 128
#define BK 16

__global__ __launch_bounds__(256) void gemm_nt_kernel(
    const float* __restrict__ A, const float* __restrict__ B,
    const float* __restrict__ bias, float* __restrict__ C,
    int M, int N, int K)
{
    __shared__ float As[BK][BM + 4];
    __shared__ float Bs[BK][BN + 4];

    const int tid  = threadIdx.x;
    const int tx   = tid & 15;        // 16 col-groups
    const int ty   = tid >> 4;        // 16 row-groups
    const int row0 = blockIdx.y * BM;
    const int col0 = blockIdx.x * BN;

    float acc[8][8];
    #pragma unroll
    for (int i = 0; i < 8; i++)
        #pragma unroll
        for (int j = 0; j < 8; j++) acc[i][j] = 0.f;

    for (int k0 = 0; k0 < K; k0 += BK) {
        // Load A and B tiles (128 rows x 16 k), transposed into smem [k][row].
        // 512 float4 per tile, 256 threads -> 2 float4 each per tile.
        #pragma unroll
        for (int i = 0; i < 2; i++) {
            const int f = tid + i * 256;
            const int r = f >> 2;
            const int c = (f & 3) << 2;
            float4 va = *reinterpret_cast<const float4*>(
                &A[(size_t)(row0 + r) * K + k0 + c]);
            As[c + 0][r] = va.x; As[c + 1][r] = va.y;
            As[c + 2][r] = va.z; As[c + 3][r] = va.w;
            float4 vb = *reinterpret_cast<const float4*>(
                &B[(size_t)(col0 + r) * K + k0 + c]);
            Bs[c + 0][r] = vb.x; Bs[c + 1][r] = vb.y;
            Bs[c + 2][r] = vb.z; Bs[c + 3][r] = vb.w;
        }
        __syncthreads();

        #pragma unroll
        for (int k = 0; k < BK; k++) {
            float ra[8], rb[8];
            #pragma unroll
            for (int i = 0; i < 8; i++) ra[i] = As[k][ty * 8 + i];
            #pragma unroll
            for (int j = 0; j < 8; j++) rb[j] = Bs[k][tx * 8 + j];
            #pragma unroll
            for (int i = 0; i < 8; i++)
                #pragma unroll
                for (int j = 0; j < 8; j++)
                    acc[i][j] += ra[i] * rb[j];
        }
        __syncthreads();
    }

    #pragma unroll
    for (int i = 0; i < 8; i++) {
        const int r = row0 + ty * 8 + i;
        #pragma unroll
        for (int j = 0; j < 8; j++) {
            const int c = col0 + tx * 8 + j;
            float v = acc[i][j];
            if (bias) v += bias[c];
            C[(size_t)r * N + c] = v;
        }
    }
}

// ---------------------------------------------------------------------------
// Per-token head-mixing attention + permuted store.
// For token t=(b,n): q,k,v are [16][64] slices of the projected tensors.
//   logits[h][g] = (q[h] . k[g]) * 64^-0.5 ; softmax over g ; out[h] = logits.v
// Output written directly in the reference's transpose(1,2).reshape(B,N,C)
// layout: element (b,h,n,d) -> Y[b][h*128 + n/16][(n%16)*64 + d].
// One block (128 threads) per token.
// q/k smem padded to stride 65 so the logits dot (lane-varying g at fixed d,
// address g*stride+d) hits distinct banks instead of a 16-way conflict.
// ---------------------------------------------------------------------------
__global__ __launch_bounds__(128) void attn_kernel(
    const float* __restrict__ Q, const float* __restrict__ K,
    const float* __restrict__ V, float* __restrict__ Y)
{
    const int t = blockIdx.x;
    const int n = t & (SEQ - 1);
    const int b = t >> 11;

    const float* q = Q + (size_t)t * DIM;
    const float* k = K + (size_t)t * DIM;
    const float* v = V + (size_t)t * DIM;

    __shared__ float sq[HEADS * 65];
    __shared__ float sk[HEADS * 65];
    __shared__ float sv[DIM];
    __shared__ float sl[HEADS * HEADS];

    const int tid = threadIdx.x;

    // Load q,k (padded) and v (linear) into smem: 256 float4 per tensor.
    #pragma unroll
    for (int i = tid; i < 256; i += 128) {
        const int r = i >> 4;
        const int c = (i & 15) << 2;
        float4 a = reinterpret_cast<const float4*>(q)[i];
        sq[r * 65 + c + 0] = a.x; sq[r * 65 + c + 1] = a.y;
        sq[r * 65 + c + 2] = a.z; sq[r * 65 + c + 3] = a.w;
        float4 bb = reinterpret_cast<const float4*>(k)[i];
        sk[r * 65 + c + 0] = bb.x; sk[r * 65 + c + 1] = bb.y;
        sk[r * 65 + c + 2] = bb.z; sk[r * 65 + c + 3] = bb.w;
        reinterpret_cast<float4*>(sv)[i] = reinterpret_cast<const float4*>(v)[i];
    }
    __syncthreads();

    // Logits: 256 entries, 2 per thread.
    #pragma unroll
    for (int e = tid; e < 256; e += 128) {
        const int h = e >> 4;
        const int g = e & 15;
        float s = 0.f;
        #pragma unroll
        for (int d = 0; d < HDIM; d++)
            s += sq[h * 65 + d] * sk[g * 65 + d];
        sl[h * 16 + g] = s * 0.125f;   // SCALE = 64^-0.5
    }
    __syncthreads();

    // Softmax over g: one thread per head row.
    if (tid < HEADS) {
        float mx = -1e30f;
        #pragma unroll
        for (int g = 0; g < 16; g++) mx = fmaxf(mx, sl[tid * 16 + g]);
        float sum = 0.f;
        #pragma unroll
        for (int g = 0; g < 16; g++) {
            const float e = __expf(sl[tid * 16 + g] - mx);
            sl[tid * 16 + g] = e;
            sum += e;
        }
        const float inv = 1.f / sum;
        #pragma unroll
        for (int g = 0; g < 16; g++) sl[tid * 16 + g] *= inv;
    }
    __syncthreads();

    // out[h][d] = sum_g attn[h][g] * v[g][d]; permuted store.
    float* yb = Y + (size_t)b * (SEQ * DIM);
    #pragma unroll
    for (int e = tid; e < 1024; e += 128) {
        const int h = e >> 6;
        const int d = e & 63;
        float s = 0.f;
        #pragma unroll
        for (int g = 0; g < 16; g++)
            s += sl[h * 16 + g] * sv[g * 64 + d];
        const int nn = h * 128 + (n >> 4);
        const int cc = ((n & 15) << 6) + d;
        yb[(size_t)nn * DIM + cc] = s;
    }
}

// ---------------------------------------------------------------------------
// kernel_launch: 3 projection GEMMs -> attention/permute -> output GEMM+bias
// Inputs (metadata order): query, key, value, xpos, ypos, Wq, Wk, Wv, Wp, bp
// xpos/ypos unused (rope is None in this config).
// ---------------------------------------------------------------------------
extern "C" void kernel_launch(void* const* d_in, const int* in_sizes, int n_in,
                              void* d_out, int out_size)
{
    const float* query = (const float*)d_in[0];
    const float* key   = (const float*)d_in[1];
    const float* value = (const float*)d_in[2];
    const float* Wq    = (const float*)d_in[5];
    const float* Wk    = (const float*)d_in[6];
    const float* Wv    = (const float*)d_in[7];
    const float* Wp    = (const float*)d_in[8];
    const float* bp    = (const float*)d_in[9];
    float* out = (float*)d_out;

    float *Qb, *Kb, *Vb, *Yb;
    cudaGetSymbolAddress((void**)&Qb, g_Q);
    cudaGetSymbolAddress((void**)&Kb, g_K);
    cudaGetSymbolAddress((void**)&Vb, g_V);
    cudaGetSymbolAddress((void**)&Yb, g_Y);

    const dim3 grid(DIM / BN, TOKENS / BM);   // (8, 128)

    gemm_nt_kernel<<<grid, 256>>>(query, Wq, nullptr, Qb, TOKENS, DIM, DIM);
    gemm_nt_kernel<<<grid, 256>>>(key,   Wk, nullptr, Kb, TOKENS, DIM, DIM);
    gemm_nt_kernel<<<grid, 256>>>(value, Wv, nullptr, Vb, TOKENS, DIM, DIM);

    attn_kernel<<<TOKENS, 128>>>(Qb, Kb, Vb, Yb);

    gemm_nt_kernel<<<grid, 256>>>(Yb, Wp, bp, out, TOKENS, DIM, DIM);
}

// round 3
// speedup vs baseline: 1.9460x; 1.9460x over previous
#include <cuda_runtime.h>
#include <cuda_bf16.h>
#include <cstdint>
#include <cstddef>

// ---------------------------------------------------------------------------
// Problem constants
// ---------------------------------------------------------------------------
#define BATCH   8
#define SEQ     2048
#define DIM     1024
#define HEADS   16
#define HDIM    64
#define TOKENS  (BATCH * SEQ)          // 16384
#define ELEMS   (TOKENS * DIM)         // 16,777,216

// ---------------------------------------------------------------------------
// Scratch (allocation-free rule: __device__ globals)
// ---------------------------------------------------------------------------
__device__ __align__(256) float g_Q[ELEMS];
__device__ __align__(256) float g_K[ELEMS];
__device__ __align__(256) float g_V[ELEMS];
__device__ __align__(256) __nv_bfloat16 g_Ahi[ELEMS];
__device__ __align__(256) __nv_bfloat16 g_Alo[ELEMS];
__device__ __align__(256) __nv_bfloat16 g_Yhi[ELEMS];
__device__ __align__(256) __nv_bfloat16 g_Ylo[ELEMS];
__device__ __align__(256) __nv_bfloat16 g_Whi[4][DIM * DIM];
__device__ __align__(256) __nv_bfloat16 g_Wlo[4][DIM * DIM];

// ---------------------------------------------------------------------------
// PTX helpers (sm_80-level features only: mma.sync / ldmatrix / cp.async —
// no tcgen05, which the harness's compute_103 virtual arch rejects)
// ---------------------------------------------------------------------------
__device__ __forceinline__ uint32_t smem_u32(const void* p) {
    uint32_t a;
    asm("{ .reg .u64 t; cvta.to.shared.u64 t, %1; cvt.u32.u64 %0, t; }"
        : "=r"(a) : "l"(p));
    return a;
}

__device__ __forceinline__ void cp_async16(uint32_t dst, const void* src) {
    asm volatile("cp.async.cg.shared.global [%0], [%1], 16;"
                 :: "r"(dst), "l"(src) : "memory");
}
__device__ __forceinline__ void cp_commit() {
    asm volatile("cp.async.commit_group;" ::: "memory");
}
template <int N>
__device__ __forceinline__ void cp_wait() {
    asm volatile("cp.async.wait_group %0;" :: "n"(N) : "memory");
}

__device__ __forceinline__ void ldm_x4(uint32_t* r, uint32_t addr) {
    asm volatile("ldmatrix.sync.aligned.m8n8.x4.shared.b16 {%0,%1,%2,%3}, [%4];"
                 : "=r"(r[0]), "=r"(r[1]), "=r"(r[2]), "=r"(r[3])
                 : "r"(addr));
}

__device__ __forceinline__ void mma_bf16(float* c, const uint32_t* a,
                                         const uint32_t* b) {
    asm volatile(
        "mma.sync.aligned.m16n8k16.row.col.f32.bf16.bf16.f32 "
        "{%0,%1,%2,%3}, {%4,%5,%6,%7}, {%8,%9}, {%0,%1,%2,%3};"
        : "+f"(c[0]), "+f"(c[1]), "+f"(c[2]), "+f"(c[3])
        : "r"(a[0]), "r"(a[1]), "r"(a[2]), "r"(a[3]), "r"(b[0]), "r"(b[1]));
}

// ---------------------------------------------------------------------------
// fp32 -> bf16 hi/lo split conversion (4 elems / thread)
// ---------------------------------------------------------------------------
__global__ __launch_bounds__(256) void convert_kernel(
    const float* __restrict__ x, __nv_bfloat16* __restrict__ hi,
    __nv_bfloat16* __restrict__ lo, int n4)
{
    int i = blockIdx.x * blockDim.x + threadIdx.x;
    if (i >= n4) return;
    float4 v = reinterpret_cast<const float4*>(x)[i];
    __nv_bfloat16 h0 = __float2bfloat16(v.x);
    __nv_bfloat16 h1 = __float2bfloat16(v.y);
    __nv_bfloat16 h2 = __float2bfloat16(v.z);
    __nv_bfloat16 h3 = __float2bfloat16(v.w);
    __nv_bfloat16 l0 = __float2bfloat16(v.x - __bfloat162float(h0));
    __nv_bfloat16 l1 = __float2bfloat16(v.y - __bfloat162float(h1));
    __nv_bfloat16 l2 = __float2bfloat16(v.z - __bfloat162float(h2));
    __nv_bfloat16 l3 = __float2bfloat16(v.w - __bfloat162float(h3));
    __nv_bfloat162 hp0(h0, h1), hp1(h2, h3), lp0(l0, l1), lp1(l2, l3);
    reinterpret_cast<__nv_bfloat162*>(hi)[i * 2 + 0] = hp0;
    reinterpret_cast<__nv_bfloat162*>(hi)[i * 2 + 1] = hp1;
    reinterpret_cast<__nv_bfloat162*>(lo)[i * 2 + 0] = lp0;
    reinterpret_cast<__nv_bfloat162*>(lo)[i * 2 + 1] = lp1;
}

// ---------------------------------------------------------------------------
// bf16x3-split GEMM-NT on mma.sync:  C = (Ahi+Alo) @ (Bhi+Blo)^T (+bias)
//   err ~ Alo*Blo dropped -> ~2^-16 relative, fp32 accum.
//   CTA 128x256, K-chunk 32, 8 warps (2x4), warp tile 64x64.
//   smem rows padded to 80B: conflict-free cp.async stores + ldmatrix reads.
// ---------------------------------------------------------------------------
#define GBM 128
#define GBN 256
#define GKC 32
#define ROWB 80                         // bytes per padded smem row (32 bf16 + pad)
#define A_T_BYTES (GBM * ROWB)          // 10240
#define B_T_BYTES (GBN * ROWB)          // 20480
#define STAGE_BYTES (2 * A_T_BYTES + 2 * B_T_BYTES)   // 61440
#define GEMM_SMEM (2 * STAGE_BYTES)                   // 122880

__global__ __launch_bounds__(256, 1) void gemm_mma_kernel(
    const __nv_bfloat16* __restrict__ Ahi, const __nv_bfloat16* __restrict__ Alo,
    const __nv_bfloat16* __restrict__ Bhi, const __nv_bfloat16* __restrict__ Blo,
    const float* __restrict__ bias, float* __restrict__ C)
{
    extern __shared__ char smem[];
    const uint32_t sbase = smem_u32(smem);

    const int tid  = threadIdx.x;
    const int wid  = tid >> 5;
    const int lane = tid & 31;
    const int wm   = wid & 1;            // 2 warp-rows  (64 rows each)
    const int wn   = wid >> 1;           // 4 warp-cols  (64 cols each)
    const int row0 = blockIdx.y * GBM;
    const int col0 = blockIdx.x * GBN;

    // ldmatrix lane addressing: row-in-16, k-halfbyte offset
    const int laneRow = (lane & 7) + ((lane >> 3) & 1) * 8;
    const int laneKB  = ((lane >> 4) & 1) * 16;

    // per-lane base offsets (within one tensor tile of a stage)
    uint32_t aoff[4], boff[4];
    #pragma unroll
    for (int mi = 0; mi < 4; mi++)
        aoff[mi] = (uint32_t)((wm * 64 + mi * 16 + laneRow) * ROWB + laneKB);
    #pragma unroll
    for (int p = 0; p < 4; p++)
        boff[p] = (uint32_t)((wn * 64 + p * 16 + laneRow) * ROWB + laneKB);

    float acc[4][8][4];
    #pragma unroll
    for (int mi = 0; mi < 4; mi++)
        #pragma unroll
        for (int ni = 0; ni < 8; ni++)
            #pragma unroll
            for (int r = 0; r < 4; r++) acc[mi][ni][r] = 0.f;

    // chunk loader: 3072 x 16B cp.async -> 12 per thread
    auto load_chunk = [&](int stage, int k0) {
        const uint32_t sb = sbase + stage * STAGE_BYTES;
        // A hi/lo: 1024 transfers
        #pragma unroll
        for (int it = 0; it < 4; it++) {
            const int i = tid + it * 256;
            const int j = i & 511, r = j >> 2, c = j & 3;
            const __nv_bfloat16* base = (i < 512) ? Ahi : Alo;
            const uint32_t off = (i < 512) ? 0u : A_T_BYTES;
            cp_async16(sb + off + r * ROWB + c * 16,
                       base + (size_t)(row0 + r) * DIM + k0 + c * 8);
        }
        // B hi/lo: 2048 transfers
        #pragma unroll
        for (int it = 0; it < 8; it++) {
            const int i = tid + it * 256;
            const int j = i & 1023, r = j >> 2, c = j & 3;
            const __nv_bfloat16* base = (i < 1024) ? Bhi : Blo;
            const uint32_t off = 2 * A_T_BYTES + ((i < 1024) ? 0u : B_T_BYTES);
            cp_async16(sb + off + r * ROWB + c * 16,
                       base + (size_t)(col0 + r) * DIM + k0 + c * 8);
        }
    };

    load_chunk(0, 0);
    cp_commit();

    const int NCHUNK = DIM / GKC;   // 32
    for (int c = 0; c < NCHUNK; c++) {
        const int s = c & 1;
        if (c + 1 < NCHUNK) {
            load_chunk(s ^ 1, (c + 1) * GKC);
            cp_commit();
            cp_wait<1>();
        } else {
            cp_wait<0>();
        }
        __syncthreads();

        const uint32_t sb  = sbase + s * STAGE_BYTES;
        const uint32_t sAh = sb;
        const uint32_t sAl = sb + A_T_BYTES;
        const uint32_t sBh = sb + 2 * A_T_BYTES;
        const uint32_t sBl = sBh + B_T_BYTES;

        #pragma unroll
        for (int ks = 0; ks < 2; ks++) {
            const uint32_t kb = (uint32_t)(ks * 32);
            uint32_t a_hi[4][4], a_lo[4][4], b_hi[8][2], b_lo[8][2];
            #pragma unroll
            for (int mi = 0; mi < 4; mi++) {
                ldm_x4(a_hi[mi], sAh + aoff[mi] + kb);
                ldm_x4(a_lo[mi], sAl + aoff[mi] + kb);
            }
            #pragma unroll
            for (int p = 0; p < 4; p++) {
                uint32_t r[4];
                ldm_x4(r, sBh + boff[p] + kb);
                b_hi[2*p][0] = r[0]; b_hi[2*p][1] = r[2];
                b_hi[2*p+1][0] = r[1]; b_hi[2*p+1][1] = r[3];
                ldm_x4(r, sBl + boff[p] + kb);
                b_lo[2*p][0] = r[0]; b_lo[2*p][1] = r[2];
                b_lo[2*p+1][0] = r[1]; b_lo[2*p+1][1] = r[3];
            }
            #pragma unroll
            for (int mi = 0; mi < 4; mi++)
                #pragma unroll
                for (int ni = 0; ni < 8; ni++) {
                    mma_bf16(acc[mi][ni], a_hi[mi], b_hi[ni]);
                    mma_bf16(acc[mi][ni], a_hi[mi], b_lo[ni]);
                    mma_bf16(acc[mi][ni], a_lo[mi], b_hi[ni]);
                }
        }
        __syncthreads();
    }

    // epilogue: C fragment -> gmem (2-float vector stores)
    const int g  = lane >> 2;
    const int tg = lane & 3;
    #pragma unroll
    for (int mi = 0; mi < 4; mi++) {
        const int r0 = row0 + wm * 64 + mi * 16 + g;
        #pragma unroll
        for (int ni = 0; ni < 8; ni++) {
            const int cc = col0 + wn * 64 + ni * 8 + tg * 2;
            float b0 = 0.f, b1 = 0.f;
            if (bias) { b0 = bias[cc]; b1 = bias[cc + 1]; }
            float2 v0 = make_float2(acc[mi][ni][0] + b0, acc[mi][ni][1] + b1);
            float2 v1 = make_float2(acc[mi][ni][2] + b0, acc[mi][ni][3] + b1);
            *reinterpret_cast<float2*>(&C[(size_t)r0 * DIM + cc]) = v0;
            *reinterpret_cast<float2*>(&C[(size_t)(r0 + 8) * DIM + cc]) = v1;
        }
    }
}

// ---------------------------------------------------------------------------
// Per-token head-mixing attention + permuted store, fused bf16 hi/lo output.
// ---------------------------------------------------------------------------
__global__ __launch_bounds__(128) void attn_kernel(
    const float* __restrict__ Q, const float* __restrict__ K,
    const float* __restrict__ V,
    __nv_bfloat16* __restrict__ Yhi, __nv_bfloat16* __restrict__ Ylo)
{
    const int t = blockIdx.x;
    const int n = t & (SEQ - 1);
    const int b = t >> 11;

    const float* q = Q + (size_t)t * DIM;
    const float* k = K + (size_t)t * DIM;
    const float* v = V + (size_t)t * DIM;

    __shared__ float sq[HEADS * 65];
    __shared__ float sk[HEADS * 65];
    __shared__ float sv[DIM];
    __shared__ float sl[HEADS * HEADS];

    const int tid = threadIdx.x;

    #pragma unroll
    for (int i = tid; i < 256; i += 128) {
        const int r = i >> 4;
        const int c = (i & 15) << 2;
        float4 a = reinterpret_cast<const float4*>(q)[i];
        sq[r * 65 + c + 0] = a.x; sq[r * 65 + c + 1] = a.y;
        sq[r * 65 + c + 2] = a.z; sq[r * 65 + c + 3] = a.w;
        float4 bb = reinterpret_cast<const float4*>(k)[i];
        sk[r * 65 + c + 0] = bb.x; sk[r * 65 + c + 1] = bb.y;
        sk[r * 65 + c + 2] = bb.z; sk[r * 65 + c + 3] = bb.w;
        reinterpret_cast<float4*>(sv)[i] = reinterpret_cast<const float4*>(v)[i];
    }
    __syncthreads();

    #pragma unroll
    for (int e = tid; e < 256; e += 128) {
        const int h = e >> 4;
        const int gg = e & 15;
        float s = 0.f;
        #pragma unroll
        for (int d = 0; d < HDIM; d++)
            s += sq[h * 65 + d] * sk[gg * 65 + d];
        sl[h * 16 + gg] = s * 0.125f;
    }
    __syncthreads();

    if (tid < HEADS) {
        float mx = -1e30f;
        #pragma unroll
        for (int gg = 0; gg < 16; gg++) mx = fmaxf(mx, sl[tid * 16 + gg]);
        float sum = 0.f;
        #pragma unroll
        for (int gg = 0; gg < 16; gg++) {
            const float e = __expf(sl[tid * 16 + gg] - mx);
            sl[tid * 16 + gg] = e;
            sum += e;
        }
        const float inv = 1.f / sum;
        #pragma unroll
        for (int gg = 0; gg < 16; gg++) sl[tid * 16 + gg] *= inv;
    }
    __syncthreads();

    const size_t ybase = (size_t)b * (SEQ * DIM);
    #pragma unroll
    for (int e = tid; e < 1024; e += 128) {
        const int h = e >> 6;
        const int d = e & 63;
        float s = 0.f;
        #pragma unroll
        for (int gg = 0; gg < 16; gg++)
            s += sl[h * 16 + gg] * sv[gg * 64 + d];
        const int nn = h * 128 + (n >> 4);
        const int cc = ((n & 15) << 6) + d;
        const size_t idx = ybase + (size_t)nn * DIM + cc;
        const __nv_bfloat16 hh = __float2bfloat16(s);
        Yhi[idx] = hh;
        Ylo[idx] = __float2bfloat16(s - __bfloat162float(hh));
    }
}

// ---------------------------------------------------------------------------
// kernel_launch
// ---------------------------------------------------------------------------
extern "C" void kernel_launch(void* const* d_in, const int* in_sizes, int n_in,
                              void* d_out, int out_size)
{
    const float* query = (const float*)d_in[0];
    const float* key   = (const float*)d_in[1];
    const float* value = (const float*)d_in[2];
    const float* W[4]  = { (const float*)d_in[5], (const float*)d_in[6],
                           (const float*)d_in[7], (const float*)d_in[8] };
    const float* bp    = (const float*)d_in[9];
    float* out = (float*)d_out;

    float *Qb, *Kb, *Vb;
    __nv_bfloat16 *Ahi, *Alo, *Yhi, *Ylo, *Whi, *Wlo;
    cudaGetSymbolAddress((void**)&Qb, g_Q);
    cudaGetSymbolAddress((void**)&Kb, g_K);
    cudaGetSymbolAddress((void**)&Vb, g_V);
    cudaGetSymbolAddress((void**)&Ahi, g_Ahi);
    cudaGetSymbolAddress((void**)&Alo, g_Alo);
    cudaGetSymbolAddress((void**)&Yhi, g_Yhi);
    cudaGetSymbolAddress((void**)&Ylo, g_Ylo);
    cudaGetSymbolAddress((void**)&Whi, g_Whi);
    cudaGetSymbolAddress((void**)&Wlo, g_Wlo);

    cudaFuncSetAttribute(gemm_mma_kernel,
                         cudaFuncAttributeMaxDynamicSharedMemorySize, GEMM_SMEM);

    // weight hi/lo splits
    for (int w = 0; w < 4; w++)
        convert_kernel<<<1024, 256>>>(W[w], Whi + (size_t)w * DIM * DIM,
                                      Wlo + (size_t)w * DIM * DIM, DIM * DIM / 4);

    const dim3 ggrid(DIM / GBN, TOKENS / GBM);   // (4, 128)
    const float* inputs[3] = { query, key, value };
    float* projout[3] = { Qb, Kb, Vb };
    for (int p = 0; p < 3; p++) {
        convert_kernel<<<16384, 256>>>(inputs[p], Ahi, Alo, ELEMS / 4);
        gemm_mma_kernel<<<ggrid, 256, GEMM_SMEM>>>(
            Ahi, Alo, Whi + (size_t)p * DIM * DIM, Wlo + (size_t)p * DIM * DIM,
            nullptr, projout[p]);
    }

    attn_kernel<<<TOKENS, 128>>>(Qb, Kb, Vb, Yhi, Ylo);

    gemm_mma_kernel<<<ggrid, 256, GEMM_SMEM>>>(
        Yhi, Ylo, Whi + (size_t)3 * DIM * DIM, Wlo + (size_t)3 * DIM * DIM,
        bp, out);
}

// round 4
// speedup vs baseline: 2.2706x; 1.1668x over previous
#include <cuda_runtime.h>
#include <cuda_bf16.h>
#include <cstdint>
#include <cstddef>

// ---------------------------------------------------------------------------
// Problem constants
// ---------------------------------------------------------------------------
#define BATCH   8
#define SEQ     2048
#define DIM     1024
#define HEADS   16
#define HDIM    64
#define TOKENS  (BATCH * SEQ)          // 16384
#define ELEMS   (TOKENS * DIM)         // 16,777,216

// ---------------------------------------------------------------------------
// Scratch (allocation-free rule: __device__ globals)
// ---------------------------------------------------------------------------
__device__ __align__(256) float g_Q[ELEMS];
__device__ __align__(256) float g_K[ELEMS];
__device__ __align__(256) float g_V[ELEMS];
__device__ __align__(256) __nv_bfloat16 g_Ahi[ELEMS];
__device__ __align__(256) __nv_bfloat16 g_Alo[ELEMS];
__device__ __align__(256) __nv_bfloat16 g_Yhi[ELEMS];
__device__ __align__(256) __nv_bfloat16 g_Ylo[ELEMS];
__device__ __align__(256) __nv_bfloat16 g_Whi[4][DIM * DIM];
__device__ __align__(256) __nv_bfloat16 g_Wlo[4][DIM * DIM];

// ---------------------------------------------------------------------------
// PTX helpers (sm_80-level only; tcgen05 rejected by compute_103 virtual arch)
// ---------------------------------------------------------------------------
__device__ __forceinline__ uint32_t smem_u32(const void* p) {
    uint32_t a;
    asm("{ .reg .u64 t; cvta.to.shared.u64 t, %1; cvt.u32.u64 %0, t; }"
        : "=r"(a) : "l"(p));
    return a;
}

__device__ __forceinline__ void cp_async16(uint32_t dst, const void* src) {
    asm volatile("cp.async.cg.shared.global [%0], [%1], 16;"
                 :: "r"(dst), "l"(src) : "memory");
}
__device__ __forceinline__ void cp_commit() {
    asm volatile("cp.async.commit_group;" ::: "memory");
}
template <int N>
__device__ __forceinline__ void cp_wait() {
    asm volatile("cp.async.wait_group %0;" :: "n"(N) : "memory");
}

__device__ __forceinline__ void ldm_x4(uint32_t* r, uint32_t addr) {
    asm volatile("ldmatrix.sync.aligned.m8n8.x4.shared.b16 {%0,%1,%2,%3}, [%4];"
                 : "=r"(r[0]), "=r"(r[1]), "=r"(r[2]), "=r"(r[3])
                 : "r"(addr));
}

__device__ __forceinline__ void mma_bf16(float* c, const uint32_t* a,
                                         const uint32_t* b) {
    asm volatile(
        "mma.sync.aligned.m16n8k16.row.col.f32.bf16.bf16.f32 "
        "{%0,%1,%2,%3}, {%4,%5,%6,%7}, {%8,%9}, {%0,%1,%2,%3};"
        : "+f"(c[0]), "+f"(c[1]), "+f"(c[2]), "+f"(c[3])
        : "r"(a[0]), "r"(a[1]), "r"(a[2]), "r"(a[3]), "r"(b[0]), "r"(b[1]));
}

// ---------------------------------------------------------------------------
// fp32 -> bf16 hi/lo split conversion (4 elems / thread)
// ---------------------------------------------------------------------------
__global__ __launch_bounds__(256) void convert_kernel(
    const float* __restrict__ x, __nv_bfloat16* __restrict__ hi,
    __nv_bfloat16* __restrict__ lo, int n4)
{
    int i = blockIdx.x * blockDim.x + threadIdx.x;
    if (i >= n4) return;
    float4 v = reinterpret_cast<const float4*>(x)[i];
    __nv_bfloat16 h0 = __float2bfloat16(v.x);
    __nv_bfloat16 h1 = __float2bfloat16(v.y);
    __nv_bfloat16 h2 = __float2bfloat16(v.z);
    __nv_bfloat16 h3 = __float2bfloat16(v.w);
    __nv_bfloat16 l0 = __float2bfloat16(v.x - __bfloat162float(h0));
    __nv_bfloat16 l1 = __float2bfloat16(v.y - __bfloat162float(h1));
    __nv_bfloat16 l2 = __float2bfloat16(v.z - __bfloat162float(h2));
    __nv_bfloat16 l3 = __float2bfloat16(v.w - __bfloat162float(h3));
    __nv_bfloat162 hp0(h0, h1), hp1(h2, h3), lp0(l0, l1), lp1(l2, l3);
    reinterpret_cast<__nv_bfloat162*>(hi)[i * 2 + 0] = hp0;
    reinterpret_cast<__nv_bfloat162*>(hi)[i * 2 + 1] = hp1;
    reinterpret_cast<__nv_bfloat162*>(lo)[i * 2 + 0] = lp0;
    reinterpret_cast<__nv_bfloat162*>(lo)[i * 2 + 1] = lp1;
}

// ---------------------------------------------------------------------------
// bf16x3-split GEMM-NT on mma.sync:  C = (Ahi+Alo) @ (Bhi+Blo)^T (+bias)
//   CTA 128x256, K-chunk 64 (128B swizzled rows), 2-stage cp.async pipeline.
//   8 warps (2x4), warp tile 64x64, SEQUENTIAL term phases (hh, lh, hl) to
//   keep one a[4][4] + one b[8][2] fragment set live (no register spills).
// Stage layout (96KB): Ahi@0 (16K) | Alo@16K | Bhi@32K (32K) | Blo@64K (32K)
// smem 16B-block swizzle: (row, c16) -> row*128 + 16*(c16 ^ (row&7))
// ---------------------------------------------------------------------------
#define GBM 128
#define GBN 256
#define GKC 64
#define STAGE_BYTES 98304
#define GEMM_SMEM (2 * STAGE_BYTES)     // 192 KB

__global__ __launch_bounds__(256, 1) void gemm_mma_kernel(
    const __nv_bfloat16* __restrict__ Ahi, const __nv_bfloat16* __restrict__ Alo,
    const __nv_bfloat16* __restrict__ Bhi, const __nv_bfloat16* __restrict__ Blo,
    const float* __restrict__ bias, float* __restrict__ C)
{
    extern __shared__ char smem[];
    const uint32_t sbase = smem_u32(smem);

    const int tid  = threadIdx.x;
    const int wid  = tid >> 5;
    const int lane = tid & 31;
    const int wm   = wid & 1;            // 2 warp-rows (64 rows each)
    const int wn   = wid >> 1;           // 4 warp-cols (64 cols each)
    const int row0 = blockIdx.y * GBM;
    const int col0 = blockIdx.x * GBN;

    // ldmatrix lane mapping (same fragment order as validated R3 kernel)
    const int laneRow = (lane & 7) + ((lane >> 3) & 1) * 8;
    const int hb      = (lane >> 4) & 1;          // 16B half selector

    // per-lane, per-tile precomputed row offsets and swizzle keys
    uint32_t aRow[4], bRow[4];
    uint32_t aXor[4], bXor[4];
    #pragma unroll
    for (int mi = 0; mi < 4; mi++) {
        const int r = wm * 64 + mi * 16 + laneRow;
        aRow[mi] = (uint32_t)(r * 128);
        aXor[mi] = (uint32_t)(r & 7);
    }
    #pragma unroll
    for (int p = 0; p < 4; p++) {
        const int r = wn * 64 + p * 16 + laneRow;
        bRow[p] = (uint32_t)(r * 128);
        bXor[p] = (uint32_t)(r & 7);
    }

    float acc[4][8][4];
    #pragma unroll
    for (int mi = 0; mi < 4; mi++)
        #pragma unroll
        for (int ni = 0; ni < 8; ni++)
            #pragma unroll
            for (int r = 0; r < 4; r++) acc[mi][ni][r] = 0.f;

    // chunk loader: 6144 x 16B cp.async -> 24 per thread
    // A hi/lo: 2048 (r<128, c16<8) ; B hi/lo: 4096 (r<256, c16<8)
    auto load_chunk = [&](int stage, int k0) {
        const uint32_t sb = sbase + stage * STAGE_BYTES;
        #pragma unroll
        for (int it = 0; it < 8; it++) {
            const int i = tid + it * 256;
            const int j = i & 1023, r = j >> 3, c = j & 7;
            const __nv_bfloat16* base = (i < 1024) ? Ahi : Alo;
            const uint32_t off = (i < 1024) ? 0u : 16384u;
            cp_async16(sb + off + r * 128 + 16 * (c ^ (r & 7)),
                       base + (size_t)(row0 + r) * DIM + k0 + c * 8);
        }
        #pragma unroll
        for (int it = 0; it < 16; it++) {
            const int i = tid + it * 256;
            const int j = i & 2047, r = j >> 3, c = j & 7;
            const __nv_bfloat16* base = (i < 2048) ? Bhi : Blo;
            const uint32_t off = 32768u + ((i < 2048) ? 0u : 32768u);
            cp_async16(sb + off + r * 128 + 16 * (c ^ (r & 7)),
                       base + (size_t)(col0 + r) * DIM + k0 + c * 8);
        }
    };

    load_chunk(0, 0);
    cp_commit();

    const int NCHUNK = DIM / GKC;   // 16
    for (int c = 0; c < NCHUNK; c++) {
        const int s = c & 1;
        if (c + 1 < NCHUNK) {
            load_chunk(s ^ 1, (c + 1) * GKC);
            cp_commit();
            cp_wait<1>();
        } else {
            cp_wait<0>();
        }
        __syncthreads();

        const uint32_t sb  = sbase + s * STAGE_BYTES;
        const uint32_t sAh = sb;
        const uint32_t sAl = sb + 16384u;
        const uint32_t sBh = sb + 32768u;
        const uint32_t sBl = sb + 65536u;

        #pragma unroll
        for (int ks = 0; ks < 4; ks++) {
            const uint32_t ck = (uint32_t)(2 * ks + hb);   // 16B column index
            uint32_t a[4][4], b[8][2];

            // phase 1: hh  (a <- Ahi, b <- Bhi)
            #pragma unroll
            for (int mi = 0; mi < 4; mi++)
                ldm_x4(a[mi], sAh + aRow[mi] + 16 * (ck ^ aXor[mi]));
            #pragma unroll
            for (int p = 0; p < 4; p++) {
                uint32_t r[4];
                ldm_x4(r, sBh + bRow[p] + 16 * (ck ^ bXor[p]));
                b[2*p][0] = r[0]; b[2*p][1] = r[2];
                b[2*p+1][0] = r[1]; b[2*p+1][1] = r[3];
            }
            #pragma unroll
            for (int mi = 0; mi < 4; mi++)
                #pragma unroll
                for (int ni = 0; ni < 8; ni++)
                    mma_bf16(acc[mi][ni], a[mi], b[ni]);

            // phase 2: lh  (a <- Alo, b stays Bhi)
            #pragma unroll
            for (int mi = 0; mi < 4; mi++)
                ldm_x4(a[mi], sAl + aRow[mi] + 16 * (ck ^ aXor[mi]));
            #pragma unroll
            for (int mi = 0; mi < 4; mi++)
                #pragma unroll
                for (int ni = 0; ni < 8; ni++)
                    mma_bf16(acc[mi][ni], a[mi], b[ni]);

            // phase 3: hl  (a <- Ahi, b <- Blo)
            #pragma unroll
            for (int mi = 0; mi < 4; mi++)
                ldm_x4(a[mi], sAh + aRow[mi] + 16 * (ck ^ aXor[mi]));
            #pragma unroll
            for (int p = 0; p < 4; p++) {
                uint32_t r[4];
                ldm_x4(r, sBl + bRow[p] + 16 * (ck ^ bXor[p]));
                b[2*p][0] = r[0]; b[2*p][1] = r[2];
                b[2*p+1][0] = r[1]; b[2*p+1][1] = r[3];
            }
            #pragma unroll
            for (int mi = 0; mi < 4; mi++)
                #pragma unroll
                for (int ni = 0; ni < 8; ni++)
                    mma_bf16(acc[mi][ni], a[mi], b[ni]);
        }
        __syncthreads();
    }

    // epilogue
    const int g  = lane >> 2;
    const int tg = lane & 3;
    #pragma unroll
    for (int mi = 0; mi < 4; mi++) {
        const int r0 = row0 + wm * 64 + mi * 16 + g;
        #pragma unroll
        for (int ni = 0; ni < 8; ni++) {
            const int cc = col0 + wn * 64 + ni * 8 + tg * 2;
            float b0 = 0.f, b1 = 0.f;
            if (bias) { b0 = bias[cc]; b1 = bias[cc + 1]; }
            float2 v0 = make_float2(acc[mi][ni][0] + b0, acc[mi][ni][1] + b1);
            float2 v1 = make_float2(acc[mi][ni][2] + b0, acc[mi][ni][3] + b1);
            *reinterpret_cast<float2*>(&C[(size_t)r0 * DIM + cc]) = v0;
            *reinterpret_cast<float2*>(&C[(size_t)(r0 + 8) * DIM + cc]) = v1;
        }
    }
}

// ---------------------------------------------------------------------------
// Per-token head-mixing attention + permuted store, fused bf16 hi/lo output.
// ---------------------------------------------------------------------------
__global__ __launch_bounds__(128) void attn_kernel(
    const float* __restrict__ Q, const float* __restrict__ K,
    const float* __restrict__ V,
    __nv_bfloat16* __restrict__ Yhi, __nv_bfloat16* __restrict__ Ylo)
{
    const int t = blockIdx.x;
    const int n = t & (SEQ - 1);
    const int b = t >> 11;

    const float* q = Q + (size_t)t * DIM;
    const float* k = K + (size_t)t * DIM;
    const float* v = V + (size_t)t * DIM;

    __shared__ float sq[HEADS * 65];
    __shared__ float sk[HEADS * 65];
    __shared__ float sv[DIM];
    __shared__ float sl[HEADS * HEADS];

    const int tid = threadIdx.x;

    #pragma unroll
    for (int i = tid; i < 256; i += 128) {
        const int r = i >> 4;
        const int c = (i & 15) << 2;
        float4 a = reinterpret_cast<const float4*>(q)[i];
        sq[r * 65 + c + 0] = a.x; sq[r * 65 + c + 1] = a.y;
        sq[r * 65 + c + 2] = a.z; sq[r * 65 + c + 3] = a.w;
        float4 bb = reinterpret_cast<const float4*>(k)[i];
        sk[r * 65 + c + 0] = bb.x; sk[r * 65 + c + 1] = bb.y;
        sk[r * 65 + c + 2] = bb.z; sk[r * 65 + c + 3] = bb.w;
        reinterpret_cast<float4*>(sv)[i] = reinterpret_cast<const float4*>(v)[i];
    }
    __syncthreads();

    #pragma unroll
    for (int e = tid; e < 256; e += 128) {
        const int h = e >> 4;
        const int gg = e & 15;
        float s = 0.f;
        #pragma unroll
        for (int d = 0; d < HDIM; d++)
            s += sq[h * 65 + d] * sk[gg * 65 + d];
        sl[h * 16 + gg] = s * 0.125f;
    }
    __syncthreads();

    if (tid < HEADS) {
        float mx = -1e30f;
        #pragma unroll
        for (int gg = 0; gg < 16; gg++) mx = fmaxf(mx, sl[tid * 16 + gg]);
        float sum = 0.f;
        #pragma unroll
        for (int gg = 0; gg < 16; gg++) {
            const float e = __expf(sl[tid * 16 + gg] - mx);
            sl[tid * 16 + gg] = e;
            sum += e;
        }
        const float inv = 1.f / sum;
        #pragma unroll
        for (int gg = 0; gg < 16; gg++) sl[tid * 16 + gg] *= inv;
    }
    __syncthreads();

    const size_t ybase = (size_t)b * (SEQ * DIM);
    #pragma unroll
    for (int e = tid; e < 1024; e += 128) {
        const int h = e >> 6;
        const int d = e & 63;
        float s = 0.f;
        #pragma unroll
        for (int gg = 0; gg < 16; gg++)
            s += sl[h * 16 + gg] * sv[gg * 64 + d];
        const int nn = h * 128 + (n >> 4);
        const int cc = ((n & 15) << 6) + d;
        const size_t idx = ybase + (size_t)nn * DIM + cc;
        const __nv_bfloat16 hh = __float2bfloat16(s);
        Yhi[idx] = hh;
        Ylo[idx] = __float2bfloat16(s - __bfloat162float(hh));
    }
}

// ---------------------------------------------------------------------------
// kernel_launch
// ---------------------------------------------------------------------------
extern "C" void kernel_launch(void* const* d_in, const int* in_sizes, int n_in,
                              void* d_out, int out_size)
{
    const float* query = (const float*)d_in[0];
    const float* key   = (const float*)d_in[1];
    const float* value = (const float*)d_in[2];
    const float* W[4]  = { (const float*)d_in[5], (const float*)d_in[6],
                           (const float*)d_in[7], (const float*)d_in[8] };
    const float* bp    = (const float*)d_in[9];
    float* out = (float*)d_out;

    float *Qb, *Kb, *Vb;
    __nv_bfloat16 *Ahi, *Alo, *Yhi, *Ylo, *Whi, *Wlo;
    cudaGetSymbolAddress((void**)&Qb, g_Q);
    cudaGetSymbolAddress((void**)&Kb, g_K);
    cudaGetSymbolAddress((void**)&Vb, g_V);
    cudaGetSymbolAddress((void**)&Ahi, g_Ahi);
    cudaGetSymbolAddress((void**)&Alo, g_Alo);
    cudaGetSymbolAddress((void**)&Yhi, g_Yhi);
    cudaGetSymbolAddress((void**)&Ylo, g_Ylo);
    cudaGetSymbolAddress((void**)&Whi, g_Whi);
    cudaGetSymbolAddress((void**)&Wlo, g_Wlo);

    cudaFuncSetAttribute(gemm_mma_kernel,
                         cudaFuncAttributeMaxDynamicSharedMemorySize, GEMM_SMEM);

    // weight hi/lo splits
    for (int w = 0; w < 4; w++)
        convert_kernel<<<1024, 256>>>(W[w], Whi + (size_t)w * DIM * DIM,
                                      Wlo + (size_t)w * DIM * DIM, DIM * DIM / 4);

    const dim3 ggrid(DIM / GBN, TOKENS / GBM);   // (4, 128)
    const float* inputs[3] = { query, key, value };
    float* projout[3] = { Qb, Kb, Vb };
    for (int p = 0; p < 3; p++) {
        convert_kernel<<<16384, 256>>>(inputs[p], Ahi, Alo, ELEMS / 4);
        gemm_mma_kernel<<<ggrid, 256, GEMM_SMEM>>>(
            Ahi, Alo, Whi + (size_t)p * DIM * DIM, Wlo + (size_t)p * DIM * DIM,
            nullptr, projout[p]);
    }

    attn_kernel<<<TOKENS, 128>>>(Qb, Kb, Vb, Yhi, Ylo);

    gemm_mma_kernel<<<ggrid, 256, GEMM_SMEM>>>(
        Yhi, Ylo, Whi + (size_t)3 * DIM * DIM, Wlo + (size_t)3 * DIM * DIM,
        bp, out);
}